// round 12
// baseline (speedup 1.0000x reference)
#include <cuda_runtime.h>

#define D_COLS   4096
#define K_SEL    2048
#define NTHREADS 128
#define NV4      8                // float4 loads per thread = 4096/4/128
#define NWARP    (NTHREADS / 32)  // 4
#define CAND_MAX 32

#define F_PINF  __int_as_float(0x7f800000)
#define F_NINF  __int_as_float(0xff800000)
#define DENS0     1634.07f        // 4096 * phi(0)
#define INV_DENS0 6.119698e-4f    // 1 / DENS0
#define MARGIN    16.5f

// Monotone float <-> ordered-uint key mapping (total order matching float <)
__device__ __forceinline__ unsigned fkey(float f) {
    unsigned u = __float_as_uint(f);
    return u ^ ((u & 0x80000000u) ? 0xFFFFFFFFu : 0x80000000u);
}
__device__ __forceinline__ float funkey(unsigned k) {
    unsigned u = k ^ ((k & 0x80000000u) ? 0x80000000u : 0xFFFFFFFFu);
    return __uint_as_float(u);
}
__device__ __forceinline__ bool my_finite(float f) { return fabsf(f) < 3.0e38f; }

// block count of (s_row >= T): 8x LDS.128 (own data, conflict-free),
// mixed int/float accumulators, REDUX per warp, LDS.128 broadcast.
__device__ __forceinline__ int block_count_smem(const float4* s_row4, float T,
                                                int4* s_slot, int t, int lane, int wid)
{
    int   ci0 = 0, ci1 = 0;
    float cf0 = 0.f, cf1 = 0.f;
    #pragma unroll
    for (int i = 0; i < NV4; i++) {
        float4 f = s_row4[t + i * NTHREADS];
        ci0 += (f.x >= T);
        ci1 += (f.y >= T);
        cf0 += (f.z >= T) ? 1.f : 0.f;
        cf1 += (f.w >= T) ? 1.f : 0.f;
    }
    int cc = (ci0 + ci1) + (int)(cf0 + cf1);
    cc = __reduce_add_sync(0xffffffffu, cc);
    if (lane == 0) ((int*)s_slot)[wid] = cc;
    __syncthreads();
    int4 p = *s_slot;
    return (p.x + p.y) + (p.z + p.w);
}

__global__ __launch_bounds__(NTHREADS, 12) void sparsify1d_kernel(
    const float* __restrict__ x, float* __restrict__ out)
{
    __shared__ __align__(16) float s_row[D_COLS];      // 16 KB row buffer
    __shared__ __align__(16) int4  s_redi[2];
    __shared__ __align__(16) float s_redf[NWARP];
    __shared__ float s_thresh;
    __shared__ float s_csum;
    __shared__ int   s_ncand;
    __shared__ float s_cand[CAND_MAX];

    const int t    = threadIdx.x;
    const int lane = t & 31;
    const int wid  = t >> 5;
    const long long row = blockIdx.x;

    const float4* __restrict__ xr   = (const float4*)(x + row * (long long)D_COLS);
    float4* __restrict__       orow = (float4*)(out + row * (long long)D_COLS);
    float4* s_row4 = (float4*)s_row;

    if (t == 0) s_ncand = 0;      // published by probe A's reduction barrier

    // ---- load row -> smem; FUSED probe A (count v >= 0) in the LDG shadow ----
    int   ca0 = 0, ca1 = 0;
    float ca2 = 0.f, ca3 = 0.f;
    #pragma unroll
    for (int i = 0; i < NV4; i++) {
        float4 f = xr[t + i * NTHREADS];
        ca0 += (f.x >= 0.f);
        ca1 += (f.y >= 0.f);
        ca2 += (f.z >= 0.f) ? 1.f : 0.f;
        ca3 += (f.w >= 0.f) ? 1.f : 0.f;
        s_row4[t + i * NTHREADS] = f;     // own slots; no cross-thread sync needed
    }
    int cA = (ca0 + ca1) + (int)(ca2 + ca3);
    cA = __reduce_add_sync(0xffffffffu, cA);
    if (lane == 0) ((int*)&s_redi[0])[wid] = cA;
    __syncthreads();
    {
        int4 p = s_redi[0];
        cA = (p.x + p.y) + (p.z + p.w);
    }

    // ---- probe B: Newton step from 0 ----
    float T1 = (float)(cA - K_SEL) * INV_DENS0;
    int   cB = block_count_smem(s_row4, T1, &s_redi[1], t, lane, wid);

    // ---- build bracket: count(>=lo)=clo >= K > chi=count(>=hi) ----
    float lo = F_NINF, hi = F_PINF;
    int clo = D_COLS, chi = 0;
    if (cA >= K_SEL) { lo = 0.0f; clo = cA; } else { hi = 0.0f; chi = cA; }
    if (T1 > lo && T1 < hi) {
        if (cB >= K_SEL) { lo = T1; clo = cB; } else { hi = T1; chi = cB; }
    }

    // ---- probe C: margin-targeted (aims count K -/+ MARGIN from nearer end) ----
    if (clo - chi > CAND_MAX) {
        float d_lo = (float)(clo - K_SEL);
        float d_hi = (float)(K_SEL - chi);
        bool fromLo = d_lo <= d_hi;
        float e  = fromLo ? lo : hi;
        float dd = fromLo ? d_lo : d_hi;
        float inv_dens = __expf(0.5f * e * e) * INV_DENS0;
        float step = (dd + MARGIN) * inv_dens;
        float T2 = fromLo ? (lo + step) : (hi - step);
        if (T2 > lo && T2 < hi) {
            int c2 = block_count_smem(s_row4, T2, &s_redi[0], t, lane, wid);
            if (c2 >= K_SEL) { lo = T2; clo = c2; }
            else             { hi = T2; chi = c2; }
        }
    }

    float thresh = 0.f;
    bool  have_thresh = false;
    int   par = 1;

    // ---- fallback refinement loop (rare) ----
    for (int iter = 0; iter < 48; iter++) {
        int m = clo - chi;
        if (m <= CAND_MAX) break;

        unsigned klo = fkey(lo), khi = fkey(hi);
        if (khi - klo <= 1u) { thresh = lo; have_thresh = true; break; }

        bool lof = my_finite(lo), hif = my_finite(hi);
        float stepl = (float)(clo - K_SEL) + 0.5f;
        float steph = (float)(K_SEL - chi) + 0.5f;
        float Ti = lo + (hi - lo) * (stepl / (float)m);
        float Tl = lo + stepl / (DENS0 * __expf(-0.5f * lo * lo));
        float Th = hi - steph / (DENS0 * __expf(-0.5f * hi * hi));
        float T  = (lof && hif) ? Ti : (lof ? Tl : Th);
        bool ok  = (T > lo) && (T < hi) && (iter < 12);
        if (!ok) T = funkey(klo + ((khi - klo) >> 1u));   // guaranteed progress

        int cc = block_count_smem(s_row4, T, &s_redi[par], t, lane, wid);
        par ^= 1;
        if (cc >= K_SEL) { lo = T; clo = cc; }
        else             { hi = T; chi = cc; }
    }

    float total;
    if (!have_thresh) {
        // ---- single sweep: predicated sum of v>=hi + warp-guarded gather ----
        float ssel = 0.f;
        #pragma unroll
        for (int i = 0; i < NV4; i++) {
            float4 f4 = s_row4[t + i * NTHREADS];
            float fe[4] = {f4.x, f4.y, f4.z, f4.w};
            #pragma unroll
            for (int c = 0; c < 4; c++) {
                float f = fe[c];
                ssel += (f >= hi) ? f : 0.f;
                bool inr = (f >= lo) && (f < hi);
                if (__any_sync(0xffffffffu, inr)) {     // warp-uniform skip
                    if (inr) {
                        int idx = atomicAdd(&s_ncand, 1);
                        if (idx < CAND_MAX) s_cand[idx] = f;
                    }
                }
            }
        }
        ssel += __shfl_xor_sync(0xffffffffu, ssel, 16);
        ssel += __shfl_xor_sync(0xffffffffu, ssel, 8);
        ssel += __shfl_xor_sync(0xffffffffu, ssel, 4);
        ssel += __shfl_xor_sync(0xffffffffu, ssel, 2);
        ssel += __shfl_xor_sync(0xffffffffu, ssel, 1);
        if (lane == 0) s_redf[wid] = ssel;
        __syncthreads();
        float4 pf = *(const float4*)s_redf;
        float ssel_total = (pf.x + pf.y) + (pf.z + pf.w);

        // ---- warp 0: bitonic sort of <=32 candidates, pick j-th largest ----
        if (wid == 0) {
            int m2 = s_ncand;             // == clo - chi  (<= 32)
            int j  = K_SEL - chi;         // 1-indexed descending rank
            float val = (lane < m2) ? s_cand[lane] : F_NINF;
            #pragma unroll
            for (int k = 2; k <= 32; k <<= 1) {
                #pragma unroll
                for (int jj = k >> 1; jj > 0; jj >>= 1) {
                    float other = __shfl_xor_sync(0xffffffffu, val, jj);
                    bool up    = ((lane & k)  == 0);
                    bool lower = ((lane & jj) == 0);
                    float mn = fminf(val, other), mx = fmaxf(val, other);
                    val = (up == lower) ? mn : mx;   // ascending sort
                }
            }
            float th = __shfl_sync(0xffffffffu, val, 32 - j);  // j-th largest
            float cs = (val >= th) ? val : 0.f;    // -inf padding excluded
            cs += __shfl_xor_sync(0xffffffffu, cs, 16);
            cs += __shfl_xor_sync(0xffffffffu, cs, 8);
            cs += __shfl_xor_sync(0xffffffffu, cs, 4);
            cs += __shfl_xor_sync(0xffffffffu, cs, 2);
            cs += __shfl_xor_sync(0xffffffffu, cs, 1);
            if (lane == 0) { s_thresh = th; s_csum = cs; }
        }
        __syncthreads();
        thresh = s_thresh;
        total  = ssel_total + s_csum;
    } else {
        // ---- rare path: thresh known exactly; plain masked sum ----
        float ss = 0.f;
        #pragma unroll
        for (int i = 0; i < NV4; i++) {
            float4 f = s_row4[t + i * NTHREADS];
            ss += (f.x >= thresh) ? f.x : 0.f;
            ss += (f.y >= thresh) ? f.y : 0.f;
            ss += (f.z >= thresh) ? f.z : 0.f;
            ss += (f.w >= thresh) ? f.w : 0.f;
        }
        ss += __shfl_xor_sync(0xffffffffu, ss, 16);
        ss += __shfl_xor_sync(0xffffffffu, ss, 8);
        ss += __shfl_xor_sync(0xffffffffu, ss, 4);
        ss += __shfl_xor_sync(0xffffffffu, ss, 2);
        ss += __shfl_xor_sync(0xffffffffu, ss, 1);
        if (lane == 0) s_redf[wid] = ss;
        __syncthreads();
        float4 pf = *(const float4*)s_redf;
        total = (pf.x + pf.y) + (pf.z + pf.w);
    }

    float scale = (float)D_COLS / total;   // out = res * D / sum(res)

    // ---- final predicated scale + coalesced store ----
    #pragma unroll
    for (int i = 0; i < NV4; i++) {
        float4 f = s_row4[t + i * NTHREADS];
        float4 o;
        o.x = (f.x >= thresh) ? f.x * scale : 0.f;
        o.y = (f.y >= thresh) ? f.y * scale : 0.f;
        o.z = (f.z >= thresh) ? f.z * scale : 0.f;
        o.w = (f.w >= thresh) ? f.w * scale : 0.f;
        orow[t + i * NTHREADS] = o;
    }
}

extern "C" void kernel_launch(void* const* d_in, const int* in_sizes, int n_in,
                              void* d_out, int out_size)
{
    const float* x = (const float*)d_in[0];
    float* out     = (float*)d_out;
    int rows = in_sizes[0] / D_COLS;     // 16384
    sparsify1d_kernel<<<rows, NTHREADS>>>(x, out);
}

// round 13
// speedup vs baseline: 1.3052x; 1.3052x over previous
#include <cuda_runtime.h>

#define D_COLS   4096
#define K_SEL    2048
#define NTHREADS 128
#define NV4      8                // float4 per thread total
#define NREG4    4                // float4 kept in registers (elements 0..15)
#define NSM4     4                // float4 kept in smem      (elements 16..31)
#define NWARP    (NTHREADS / 32)  // 4
#define CAND_MAX 32

#define F_PINF  __int_as_float(0x7f800000)
#define F_NINF  __int_as_float(0xff800000)
#define DENS0     1634.07f        // 4096 * phi(0)
#define INV_DENS0 6.119698e-4f    // 1 / DENS0
#define MARGIN    16.5f

// Monotone float <-> ordered-uint key mapping (total order matching float <)
__device__ __forceinline__ unsigned fkey(float f) {
    unsigned u = __float_as_uint(f);
    return u ^ ((u & 0x80000000u) ? 0xFFFFFFFFu : 0x80000000u);
}
__device__ __forceinline__ float funkey(unsigned k) {
    unsigned u = k ^ ((k & 0x80000000u) ? 0x80000000u : 0xFFFFFFFFu);
    return __uint_as_float(u);
}
__device__ __forceinline__ bool my_finite(float f) { return fabsf(f) < 3.0e38f; }

__global__ __launch_bounds__(NTHREADS, 10) void sparsify1d_kernel(
    const float* __restrict__ x, float* __restrict__ out)
{
    __shared__ __align__(16) float4 s_ext[NSM4 * NTHREADS];   // 8 KB: elements 16..31
    __shared__ __align__(16) int4  s_redi[2];
    __shared__ __align__(16) float s_redf[NWARP];
    __shared__ float s_thresh;
    __shared__ float s_csum;
    __shared__ int   s_ncand;
    __shared__ float s_cand[CAND_MAX];

    const int t    = threadIdx.x;
    const int lane = t & 31;
    const int wid  = t >> 5;
    const long long row = blockIdx.x;

    const float4* __restrict__ xr   = (const float4*)(x + row * (long long)D_COLS);
    float4* __restrict__       orow = (float4*)(out + row * (long long)D_COLS);

    if (t == 0) s_ncand = 0;      // published by probe A's reduction barrier

    // ---- load row: 4 float4 -> registers, 4 float4 -> smem (own slots) ----
    // FUSED probe A (count v >= 0) in the LDG shadow.
    float v[NREG4 * 4];
    int   ca0 = 0, ca1 = 0;
    float ca2 = 0.f, ca3 = 0.f;
    #pragma unroll
    for (int i = 0; i < NREG4; i++) {
        float4 f = xr[t + i * NTHREADS];
        v[4*i+0] = f.x; v[4*i+1] = f.y; v[4*i+2] = f.z; v[4*i+3] = f.w;
        ca0 += (f.x >= 0.f);
        ca1 += (f.y >= 0.f);
        ca2 += (f.z >= 0.f) ? 1.f : 0.f;
        ca3 += (f.w >= 0.f) ? 1.f : 0.f;
    }
    #pragma unroll
    for (int i = 0; i < NSM4; i++) {
        float4 f = xr[t + (NREG4 + i) * NTHREADS];
        ca0 += (f.x >= 0.f);
        ca1 += (f.y >= 0.f);
        ca2 += (f.z >= 0.f) ? 1.f : 0.f;
        ca3 += (f.w >= 0.f) ? 1.f : 0.f;
        s_ext[i * NTHREADS + t] = f;      // own slot; barrier below orders it
    }
    int cA = (ca0 + ca1) + (int)(ca2 + ca3);
    cA = __reduce_add_sync(0xffffffffu, cA);
    if (lane == 0) ((int*)&s_redi[0])[wid] = cA;
    __syncthreads();
    {
        int4 p = s_redi[0];
        cA = (p.x + p.y) + (p.z + p.w);
    }

    // block count helper (lambda-style macro not used; inline twice via loop)
    // counts = 16 register compares + 4 LDS.128 (own data, conflict-free)
    auto block_count = [&](float T, int4* s_slot) -> int {
        int   ci0 = 0, ci1 = 0;
        float cf0 = 0.f, cf1 = 0.f;
        #pragma unroll
        for (int i = 0; i < NREG4 * 4; i += 4) {
            ci0 += (v[i+0] >= T);
            ci1 += (v[i+1] >= T);
            cf0 += (v[i+2] >= T) ? 1.f : 0.f;
            cf1 += (v[i+3] >= T) ? 1.f : 0.f;
        }
        #pragma unroll
        for (int i = 0; i < NSM4; i++) {
            float4 f = s_ext[i * NTHREADS + t];
            ci0 += (f.x >= T);
            ci1 += (f.y >= T);
            cf0 += (f.z >= T) ? 1.f : 0.f;
            cf1 += (f.w >= T) ? 1.f : 0.f;
        }
        int cc = (ci0 + ci1) + (int)(cf0 + cf1);
        cc = __reduce_add_sync(0xffffffffu, cc);
        if (lane == 0) ((int*)s_slot)[wid] = cc;
        __syncthreads();
        int4 p = *s_slot;
        return (p.x + p.y) + (p.z + p.w);
    };

    // ---- probe B: Newton step from 0 ----
    float T1 = (float)(cA - K_SEL) * INV_DENS0;
    int   cB = block_count(T1, &s_redi[1]);

    // ---- build bracket: count(>=lo)=clo >= K > chi=count(>=hi) ----
    float lo = F_NINF, hi = F_PINF;
    int clo = D_COLS, chi = 0;
    if (cA >= K_SEL) { lo = 0.0f; clo = cA; } else { hi = 0.0f; chi = cA; }
    if (T1 > lo && T1 < hi) {
        if (cB >= K_SEL) { lo = T1; clo = cB; } else { hi = T1; chi = cB; }
    }

    // ---- probe C: margin-targeted (aims count K -/+ MARGIN from nearer end) ----
    if (clo - chi > CAND_MAX) {
        float d_lo = (float)(clo - K_SEL);
        float d_hi = (float)(K_SEL - chi);
        bool fromLo = d_lo <= d_hi;
        float e  = fromLo ? lo : hi;
        float dd = fromLo ? d_lo : d_hi;
        float inv_dens = __expf(0.5f * e * e) * INV_DENS0;
        float step = (dd + MARGIN) * inv_dens;
        float T2 = fromLo ? (lo + step) : (hi - step);
        if (T2 > lo && T2 < hi) {
            int c2 = block_count(T2, &s_redi[0]);
            if (c2 >= K_SEL) { lo = T2; clo = c2; }
            else             { hi = T2; chi = c2; }
        }
    }

    float thresh = 0.f;
    bool  have_thresh = false;
    int   par = 1;

    // ---- fallback refinement loop (rare) ----
    for (int iter = 0; iter < 48; iter++) {
        int m = clo - chi;
        if (m <= CAND_MAX) break;

        unsigned klo = fkey(lo), khi = fkey(hi);
        if (khi - klo <= 1u) { thresh = lo; have_thresh = true; break; }

        bool lof = my_finite(lo), hif = my_finite(hi);
        float stepl = (float)(clo - K_SEL) + 0.5f;
        float steph = (float)(K_SEL - chi) + 0.5f;
        float Ti = lo + (hi - lo) * (stepl / (float)m);
        float Tl = lo + stepl / (DENS0 * __expf(-0.5f * lo * lo));
        float Th = hi - steph / (DENS0 * __expf(-0.5f * hi * hi));
        float T  = (lof && hif) ? Ti : (lof ? Tl : Th);
        bool ok  = (T > lo) && (T < hi) && (iter < 12);
        if (!ok) T = funkey(klo + ((khi - klo) >> 1u));   // guaranteed progress

        int cc = block_count(T, &s_redi[par]);
        par ^= 1;
        if (cc >= K_SEL) { lo = T; clo = cc; }
        else             { hi = T; chi = cc; }
    }

    float total;
    if (!have_thresh) {
        // ---- single sweep: predicated sum of v>=hi + warp-guarded gather ----
        float ssel = 0.f;
        #pragma unroll
        for (int i = 0; i < NREG4 * 4; i++) {
            float f = v[i];
            ssel += (f >= hi) ? f : 0.f;
            bool inr = (f >= lo) && (f < hi);
            if (__any_sync(0xffffffffu, inr)) {
                if (inr) {
                    int idx = atomicAdd(&s_ncand, 1);
                    if (idx < CAND_MAX) s_cand[idx] = f;
                }
            }
        }
        #pragma unroll
        for (int i = 0; i < NSM4; i++) {
            float4 f4 = s_ext[i * NTHREADS + t];
            float fe[4] = {f4.x, f4.y, f4.z, f4.w};
            #pragma unroll
            for (int c = 0; c < 4; c++) {
                float f = fe[c];
                ssel += (f >= hi) ? f : 0.f;
                bool inr = (f >= lo) && (f < hi);
                if (__any_sync(0xffffffffu, inr)) {
                    if (inr) {
                        int idx = atomicAdd(&s_ncand, 1);
                        if (idx < CAND_MAX) s_cand[idx] = f;
                    }
                }
            }
        }
        ssel += __shfl_xor_sync(0xffffffffu, ssel, 16);
        ssel += __shfl_xor_sync(0xffffffffu, ssel, 8);
        ssel += __shfl_xor_sync(0xffffffffu, ssel, 4);
        ssel += __shfl_xor_sync(0xffffffffu, ssel, 2);
        ssel += __shfl_xor_sync(0xffffffffu, ssel, 1);
        if (lane == 0) s_redf[wid] = ssel;
        __syncthreads();
        float4 pf = *(const float4*)s_redf;
        float ssel_total = (pf.x + pf.y) + (pf.z + pf.w);

        // ---- warp 0: bitonic sort of <=32 candidates, pick j-th largest ----
        if (wid == 0) {
            int m2 = s_ncand;             // == clo - chi  (<= 32)
            int j  = K_SEL - chi;         // 1-indexed descending rank
            float val = (lane < m2) ? s_cand[lane] : F_NINF;
            #pragma unroll
            for (int k = 2; k <= 32; k <<= 1) {
                #pragma unroll
                for (int jj = k >> 1; jj > 0; jj >>= 1) {
                    float other = __shfl_xor_sync(0xffffffffu, val, jj);
                    bool up    = ((lane & k)  == 0);
                    bool lower = ((lane & jj) == 0);
                    float mn = fminf(val, other), mx = fmaxf(val, other);
                    val = (up == lower) ? mn : mx;   // ascending sort
                }
            }
            float th = __shfl_sync(0xffffffffu, val, 32 - j);  // j-th largest
            float cs = (val >= th) ? val : 0.f;    // -inf padding excluded
            cs += __shfl_xor_sync(0xffffffffu, cs, 16);
            cs += __shfl_xor_sync(0xffffffffu, cs, 8);
            cs += __shfl_xor_sync(0xffffffffu, cs, 4);
            cs += __shfl_xor_sync(0xffffffffu, cs, 2);
            cs += __shfl_xor_sync(0xffffffffu, cs, 1);
            if (lane == 0) { s_thresh = th; s_csum = cs; }
        }
        __syncthreads();
        thresh = s_thresh;
        total  = ssel_total + s_csum;
    } else {
        // ---- rare path: thresh known exactly; plain masked sum ----
        float ss = 0.f;
        #pragma unroll
        for (int i = 0; i < NREG4 * 4; i++) ss += (v[i] >= thresh) ? v[i] : 0.f;
        #pragma unroll
        for (int i = 0; i < NSM4; i++) {
            float4 f = s_ext[i * NTHREADS + t];
            ss += (f.x >= thresh) ? f.x : 0.f;
            ss += (f.y >= thresh) ? f.y : 0.f;
            ss += (f.z >= thresh) ? f.z : 0.f;
            ss += (f.w >= thresh) ? f.w : 0.f;
        }
        ss += __shfl_xor_sync(0xffffffffu, ss, 16);
        ss += __shfl_xor_sync(0xffffffffu, ss, 8);
        ss += __shfl_xor_sync(0xffffffffu, ss, 4);
        ss += __shfl_xor_sync(0xffffffffu, ss, 2);
        ss += __shfl_xor_sync(0xffffffffu, ss, 1);
        if (lane == 0) s_redf[wid] = ss;
        __syncthreads();
        float4 pf = *(const float4*)s_redf;
        total = (pf.x + pf.y) + (pf.z + pf.w);
    }

    float scale = (float)D_COLS / total;   // out = res * D / sum(res)

    // ---- final predicated scale + coalesced store ----
    #pragma unroll
    for (int i = 0; i < NREG4; i++) {
        float4 o;
        o.x = (v[4*i+0] >= thresh) ? v[4*i+0] * scale : 0.f;
        o.y = (v[4*i+1] >= thresh) ? v[4*i+1] * scale : 0.f;
        o.z = (v[4*i+2] >= thresh) ? v[4*i+2] * scale : 0.f;
        o.w = (v[4*i+3] >= thresh) ? v[4*i+3] * scale : 0.f;
        orow[t + i * NTHREADS] = o;
    }
    #pragma unroll
    for (int i = 0; i < NSM4; i++) {
        float4 f = s_ext[i * NTHREADS + t];
        float4 o;
        o.x = (f.x >= thresh) ? f.x * scale : 0.f;
        o.y = (f.y >= thresh) ? f.y * scale : 0.f;
        o.z = (f.z >= thresh) ? f.z * scale : 0.f;
        o.w = (f.w >= thresh) ? f.w * scale : 0.f;
        orow[t + (NREG4 + i) * NTHREADS] = o;
    }
}

extern "C" void kernel_launch(void* const* d_in, const int* in_sizes, int n_in,
                              void* d_out, int out_size)
{
    const float* x = (const float*)d_in[0];
    float* out     = (float*)d_out;
    int rows = in_sizes[0] / D_COLS;     // 16384
    sparsify1d_kernel<<<rows, NTHREADS>>>(x, out);
}